// round 2
// baseline (speedup 1.0000x reference)
#include <cuda_runtime.h>
#include <cstdint>

// ---------------- problem-size constants (fixed by dataset) ----------------
#define NMAX 100352            // 98*1024, >= 100000 nodes
#define EMAX 1700032           // >= 1,600,000 edges

// ---------------- scratch (static __device__ — no allocations) -------------
__device__ __align__(16) float g_h1[(size_t)NMAX * 128];   // x @ W1
__device__ __align__(16) float g_a1[(size_t)NMAX * 128];   // relu(agg(h1) + b1)
__device__ __align__(16) float g_h2[(size_t)NMAX * 64];    // a1 @ W2
__device__ float g_dinv[NMAX];
__device__ int   g_deg[NMAX];
__device__ int   g_cur[NMAX];
__device__ int   g_ptr[NMAX + 1];
__device__ int   g_src[EMAX];
__device__ int   g_scan[NMAX];
__device__ int   g_bsum[128];
__device__ int   g_boff[128];
__device__ int   g_is64;

// ---------------- edge dtype detection -------------------------------------
// If edge_index is int64 (LE, values < 2^31), every odd 32-bit word is zero.
// If int32, odd words are random node ids — 128 consecutive zeros ~ impossible.
__global__ void k_detect(const unsigned int* __restrict__ w) {
    if (threadIdx.x == 0 && blockIdx.x == 0) {
        unsigned int nz = 0;
        for (int i = 1; i < 256; i += 2) nz |= w[i];
        g_is64 = (nz == 0) ? 1 : 0;
    }
}

__device__ __forceinline__ int edge_at(const void* __restrict__ ei, int i) {
    if (g_is64) return (int)((const long long*)ei)[i];
    return ((const int*)ei)[i];
}

// ---------------- small kernels --------------------------------------------
__global__ void k_zero(int n) {
    int i = blockIdx.x * blockDim.x + threadIdx.x;
    if (i < n) { g_deg[i] = 0; g_cur[i] = 0; }
}

__global__ void k_count(const void* __restrict__ ei, int E) {
    int e = blockIdx.x * blockDim.x + threadIdx.x;
    if (e < E) {
        int c = edge_at(ei, E + e);
        atomicAdd(&g_deg[c], 1);
    }
}

__global__ void k_dinv(int N) {
    int i = blockIdx.x * blockDim.x + threadIdx.x;
    if (i < N) g_dinv[i] = rsqrtf((float)(g_deg[i] + 1));  // +1 self loop
}

// block-wise inclusive scan of g_deg (1024/block)
__global__ void k_scan1(int N) {
    __shared__ int s[1024];
    int t = threadIdx.x;
    int i = blockIdx.x * 1024 + t;
    int v = (i < N) ? g_deg[i] : 0;
    s[t] = v;
    __syncthreads();
#pragma unroll
    for (int off = 1; off < 1024; off <<= 1) {
        int x = (t >= off) ? s[t - off] : 0;
        __syncthreads();
        s[t] += x;
        __syncthreads();
    }
    g_scan[i] = s[t];
    if (t == 1023) g_bsum[blockIdx.x] = s[t];
}

__global__ void k_scan2(int nb) {
    if (threadIdx.x == 0 && blockIdx.x == 0) {
        int run = 0;
        for (int b = 0; b < nb; b++) { g_boff[b] = run; run += g_bsum[b]; }
    }
}

__global__ void k_scan3(int N) {
    int i = blockIdx.x * blockDim.x + threadIdx.x;
    if (i < N) {
        g_ptr[i + 1] = g_scan[i] + g_boff[i >> 10];
        if (i == 0) g_ptr[0] = 0;
    }
}

__global__ void k_fill(const void* __restrict__ ei, int E) {
    int e = blockIdx.x * blockDim.x + threadIdx.x;
    if (e < E) {
        int r = edge_at(ei, e);
        int c = edge_at(ei, E + e);
        int pos = g_ptr[c] + atomicAdd(&g_cur[c], 1);
        g_src[pos] = r;
    }
}

// ---------------- SGEMM: C[M,BN] = A[M,128] * B[128,BN] --------------------
// BM=64, BK=16, per-thread 8x4 micro-tile. One block covers all BN columns.
// A_GLOBAL selects g_a1 as the A operand (layer 2); C is g_h1 or g_h2 by BN.
template <int BN, bool A_GLOBAL>
__global__ void k_gemm(const float* __restrict__ Ain, const float* __restrict__ B,
                       int M) {
    constexpr int BM = 64, BK = 16, TM = 8, TN = 4;
    constexpr int TX = BN / TN;                  // 32 (BN=128) or 16 (BN=64)
    constexpr int NT = (BM / TM) * TX;           // 256 or 128 threads

    const float* A = A_GLOBAL ? (const float*)g_a1 : Ain;
    float* C = (BN == 128) ? (float*)g_h1 : (float*)g_h2;

    __shared__ __align__(16) float As[BK][BM];
    __shared__ __align__(16) float Bs[BK][BN];

    int t  = threadIdx.x;
    int tx = t % TX;
    int ty = t / TX;
    int m0 = blockIdx.x * BM;

    float4 acc[TM];
#pragma unroll
    for (int i = 0; i < TM; i++) acc[i] = make_float4(0.f, 0.f, 0.f, 0.f);

    for (int k0 = 0; k0 < 128; k0 += BK) {
        // load A tile (BM x BK) transposed -> As[k][m]
#pragma unroll
        for (int task = t; task < BM * BK / 4; task += NT) {
            int m  = task % BM;
            int kp = task / BM;          // 0..3
            int row = m0 + m;
            float4 v = make_float4(0.f, 0.f, 0.f, 0.f);
            if (row < M)
                v = *(const float4*)&A[(size_t)row * 128 + k0 + kp * 4];
            As[kp * 4 + 0][m] = v.x;
            As[kp * 4 + 1][m] = v.y;
            As[kp * 4 + 2][m] = v.z;
            As[kp * 4 + 3][m] = v.w;
        }
        // load B tile (BK x BN)
#pragma unroll
        for (int task = t; task < BK * BN / 4; task += NT) {
            int n4 = task % (BN / 4);
            int kk = task / (BN / 4);
            *(float4*)&Bs[kk][n4 * 4] =
                *(const float4*)&B[(size_t)(k0 + kk) * BN + n4 * 4];
        }
        __syncthreads();

#pragma unroll
        for (int kk = 0; kk < BK; kk++) {
            float a[TM];
            *(float4*)(a)     = *(const float4*)&As[kk][ty * TM];
            *(float4*)(a + 4) = *(const float4*)&As[kk][ty * TM + 4];
            float4 b = *(const float4*)&Bs[kk][tx * TN];
#pragma unroll
            for (int i = 0; i < TM; i++) {
                acc[i].x = fmaf(a[i], b.x, acc[i].x);
                acc[i].y = fmaf(a[i], b.y, acc[i].y);
                acc[i].z = fmaf(a[i], b.z, acc[i].z);
                acc[i].w = fmaf(a[i], b.w, acc[i].w);
            }
        }
        __syncthreads();
    }

#pragma unroll
    for (int i = 0; i < TM; i++) {
        int row = m0 + ty * TM + i;
        if (row < M)
            *(float4*)&C[(size_t)row * BN + tx * TN] = acc[i];
    }
}

// ---------------- aggregation: one warp per target node --------------------
// out[c] = bias + dinv[c]^2 * h[c] + sum_{e: col==c} dinv[c]*dinv[row]*h[row]
// 128-channel variant (layer 1, with ReLU): h = g_h1, out = g_a1
__global__ void k_agg128(const float* __restrict__ bias, int N) {
    int warp = (blockIdx.x * blockDim.x + threadIdx.x) >> 5;
    int lane = threadIdx.x & 31;
    if (warp >= N) return;

    const float4* h4 = (const float4*)g_h1;
    float di = g_dinv[warp];
    float4 v = h4[(size_t)warp * 32 + lane];
    float w0 = di * di;
    float4 acc = make_float4(v.x * w0, v.y * w0, v.z * w0, v.w * w0);

    int s = g_ptr[warp], e = g_ptr[warp + 1];
    for (int j = s; j < e; j++) {
        int r = g_src[j];
        float wr = di * g_dinv[r];
        float4 hv = h4[(size_t)r * 32 + lane];
        acc.x = fmaf(wr, hv.x, acc.x);
        acc.y = fmaf(wr, hv.y, acc.y);
        acc.z = fmaf(wr, hv.z, acc.z);
        acc.w = fmaf(wr, hv.w, acc.w);
    }

    float4 b = ((const float4*)bias)[lane];
    acc.x = fmaxf(acc.x + b.x, 0.f);
    acc.y = fmaxf(acc.y + b.y, 0.f);
    acc.z = fmaxf(acc.z + b.z, 0.f);
    acc.w = fmaxf(acc.w + b.w, 0.f);
    ((float4*)g_a1)[(size_t)warp * 32 + lane] = acc;
}

// 64-channel variant (layer 2, no ReLU): h = g_h2, out = d_out
__global__ void k_agg64(const float* __restrict__ bias, float* __restrict__ out,
                        int N) {
    int warp = (blockIdx.x * blockDim.x + threadIdx.x) >> 5;
    int lane = threadIdx.x & 31;
    if (warp >= N) return;

    const float2* h2 = (const float2*)g_h2;
    float di = g_dinv[warp];
    float2 v = h2[(size_t)warp * 32 + lane];
    float w0 = di * di;
    float2 acc = make_float2(v.x * w0, v.y * w0);

    int s = g_ptr[warp], e = g_ptr[warp + 1];
    for (int j = s; j < e; j++) {
        int r = g_src[j];
        float wr = di * g_dinv[r];
        float2 hv = h2[(size_t)r * 32 + lane];
        acc.x = fmaf(wr, hv.x, acc.x);
        acc.y = fmaf(wr, hv.y, acc.y);
    }

    float2 b = ((const float2*)bias)[lane];
    acc.x += b.x;
    acc.y += b.y;
    ((float2*)out)[(size_t)warp * 32 + lane] = acc;
}

// ---------------- launch ----------------------------------------------------
extern "C" void kernel_launch(void* const* d_in, const int* in_sizes, int n_in,
                              void* d_out, int out_size) {
    const float* x  = (const float*)d_in[0];
    const void*  ei = d_in[1];                   // int32 or int64, detected on device
    const float* W1 = (const float*)d_in[2];
    const float* b1 = (const float*)d_in[3];
    const float* W2 = (const float*)d_in[4];
    const float* b2 = (const float*)d_in[5];
    float*       out = (float*)d_out;

    int N = in_sizes[0] / 128;
    int E = in_sizes[1] / 2;

    // dtype probe + degree / dinv / CSR build
    k_detect<<<1, 32>>>((const unsigned int*)ei);
    k_zero<<<(N + 255) / 256, 256>>>(N);
    k_count<<<(E + 255) / 256, 256>>>(ei, E);
    k_dinv<<<(N + 255) / 256, 256>>>(N);
    int nb = (N + 1023) / 1024;
    k_scan1<<<nb, 1024>>>(N);
    k_scan2<<<1, 32>>>(nb);
    k_scan3<<<(N + 255) / 256, 256>>>(N);
    k_fill<<<(E + 255) / 256, 256>>>(ei, E);

    // layer 1
    k_gemm<128, false><<<(N + 63) / 64, 256>>>(x, W1, N);
    k_agg128<<<(N * 32 + 255) / 256, 256>>>(b1, N);

    // layer 2
    k_gemm<64, true><<<(N + 63) / 64, 128>>>(nullptr, W2, N);
    k_agg64<<<(N * 32 + 255) / 256, 256>>>(b2, out, N);
}

// round 3
// speedup vs baseline: 1.1695x; 1.1695x over previous
#include <cuda_runtime.h>
#include <cstdint>

// ---------------- problem-size constants (fixed by dataset) ----------------
#define NMAX 100352            // 784*128, >= 100000 nodes (padded for tile overrun)
#define EMAX 1700032           // >= 1,600,000 edges

// ---------------- scratch (static __device__ — no allocations) -------------
__device__ __align__(16) float g_h1[(size_t)NMAX * 128];   // x @ W1
__device__ __align__(16) float g_a1[(size_t)NMAX * 128];   // relu(agg(h1) + b1)
__device__ __align__(16) float g_h2[(size_t)NMAX * 64];    // a1 @ W2
__device__ float g_dinv[NMAX];
__device__ int   g_deg[NMAX];
__device__ int   g_cur[NMAX];
__device__ int   g_ptr[NMAX + 1];
__device__ int   g_src[EMAX];
__device__ int   g_scan[NMAX];
__device__ int   g_bsum[128];
__device__ int   g_boff[128];
__device__ int   g_is64;

// ---------------- edge dtype detection -------------------------------------
__global__ void k_detect(const unsigned int* __restrict__ w) {
    if (threadIdx.x == 0 && blockIdx.x == 0) {
        unsigned int nz = 0;
        for (int i = 1; i < 256; i += 2) nz |= w[i];
        g_is64 = (nz == 0) ? 1 : 0;
    }
}

__device__ __forceinline__ int edge_at(const void* __restrict__ ei, int i) {
    if (g_is64) return (int)((const long long*)ei)[i];
    return ((const int*)ei)[i];
}

// ---------------- small kernels --------------------------------------------
__global__ void k_zero(int n) {
    int i = blockIdx.x * blockDim.x + threadIdx.x;
    if (i < n) { g_deg[i] = 0; g_cur[i] = 0; }
}

__global__ void k_count(const void* __restrict__ ei, int E) {
    int e = blockIdx.x * blockDim.x + threadIdx.x;
    if (e < E) atomicAdd(&g_deg[edge_at(ei, E + e)], 1);
}

__global__ void k_dinv(int N) {
    int i = blockIdx.x * blockDim.x + threadIdx.x;
    if (i < N) g_dinv[i] = rsqrtf((float)(g_deg[i] + 1));  // +1 self loop
}

__global__ void k_scan1(int N) {
    __shared__ int s[1024];
    int t = threadIdx.x;
    int i = blockIdx.x * 1024 + t;
    int v = (i < N) ? g_deg[i] : 0;
    s[t] = v;
    __syncthreads();
#pragma unroll
    for (int off = 1; off < 1024; off <<= 1) {
        int x = (t >= off) ? s[t - off] : 0;
        __syncthreads();
        s[t] += x;
        __syncthreads();
    }
    g_scan[i] = s[t];
    if (t == 1023) g_bsum[blockIdx.x] = s[t];
}

__global__ void k_scan2(int nb) {
    if (threadIdx.x == 0 && blockIdx.x == 0) {
        int run = 0;
        for (int b = 0; b < nb; b++) { g_boff[b] = run; run += g_bsum[b]; }
    }
}

__global__ void k_scan3(int N) {
    int i = blockIdx.x * blockDim.x + threadIdx.x;
    if (i < N) {
        g_ptr[i + 1] = g_scan[i] + g_boff[i >> 10];
        if (i == 0) g_ptr[0] = 0;
    }
}

__global__ void k_fill(const void* __restrict__ ei, int E) {
    int e = blockIdx.x * blockDim.x + threadIdx.x;
    if (e < E) {
        int r = edge_at(ei, e);
        int c = edge_at(ei, E + e);
        int pos = g_ptr[c] + atomicAdd(&g_cur[c], 1);
        g_src[pos] = r;
    }
}

// ---------------- tf32 tensor-core GEMM ------------------------------------
// C[M,BN] = A[M,128] * B[128,BN], A row-major, B row-major.
// Block: BM=128, BK=32, 256 threads (8 warps). mma.sync.m16n8k8.tf32.
__device__ __forceinline__ uint32_t f2tf32(float f) {
    uint32_t u;
    asm("cvt.rna.tf32.f32 %0, %1;" : "=r"(u) : "f"(f));
    return u;
}

__device__ __forceinline__ void mma_tf32(float* c, const uint32_t* a, const uint32_t* b) {
    asm volatile(
        "mma.sync.aligned.m16n8k8.row.col.f32.tf32.tf32.f32 "
        "{%0,%1,%2,%3}, {%4,%5,%6,%7}, {%8,%9}, {%0,%1,%2,%3};"
        : "+f"(c[0]), "+f"(c[1]), "+f"(c[2]), "+f"(c[3])
        : "r"(a[0]), "r"(a[1]), "r"(a[2]), "r"(a[3]), "r"(b[0]), "r"(b[1]));
}

template <int BN, bool A_GLOBAL>
__global__ void k_gemm_tf32(const float* __restrict__ Ain,
                            const float* __restrict__ B, int M) {
    constexpr int BM = 128, BK = 32;
    constexpr int NT = BN / 16;          // n-tiles of 8 per warp: 8 (BN=128) / 4 (BN=64)
    constexpr int BP = BN + 4;           // padded B pitch

    const float* A = A_GLOBAL ? (const float*)g_a1 : Ain;
    float* C = (BN == 128) ? (float*)g_h1 : (float*)g_h2;

    __shared__ uint32_t As[BM][BK + 4];
    __shared__ uint32_t Bs[BK][BP];

    int t    = threadIdx.x;
    int lane = t & 31;
    int wid  = t >> 5;
    int warp_m = (wid & 3) * 32;         // 4 warps along M
    int warp_n = (wid >> 2) * (BN / 2);  // 2 warps along N
    int m0   = blockIdx.x * BM;
    int r = lane >> 2, c4 = lane & 3;

    float acc[2][NT][4];
#pragma unroll
    for (int mt = 0; mt < 2; mt++)
#pragma unroll
        for (int nt = 0; nt < NT; nt++)
#pragma unroll
            for (int i = 0; i < 4; i++) acc[mt][nt][i] = 0.f;

    for (int k0 = 0; k0 < 128; k0 += BK) {
        // A tile (BM x BK), tf32-converted on store
#pragma unroll
        for (int t4 = t; t4 < BM * BK / 4; t4 += 256) {
            int row = t4 >> 3;
            int kq  = t4 & 7;
            int gr  = m0 + row;
            float4 v = make_float4(0.f, 0.f, 0.f, 0.f);
            if (A_GLOBAL || gr < M)
                v = *(const float4*)&A[(size_t)gr * 128 + k0 + kq * 4];
            uint32_t* dst = &As[row][kq * 4];
            dst[0] = f2tf32(v.x); dst[1] = f2tf32(v.y);
            dst[2] = f2tf32(v.z); dst[3] = f2tf32(v.w);
        }
        // B tile (BK x BN)
#pragma unroll
        for (int t4 = t; t4 < BK * BN / 4; t4 += 256) {
            int kk = t4 / (BN / 4);
            int nq = t4 % (BN / 4);
            float4 v = *(const float4*)&B[(size_t)(k0 + kk) * BN + nq * 4];
            uint32_t* dst = &Bs[kk][nq * 4];
            dst[0] = f2tf32(v.x); dst[1] = f2tf32(v.y);
            dst[2] = f2tf32(v.z); dst[3] = f2tf32(v.w);
        }
        __syncthreads();

#pragma unroll
        for (int kk = 0; kk < 4; kk++) {     // 4 k-steps of 8
            int kb = kk * 8;
            uint32_t afr[2][4];
#pragma unroll
            for (int mt = 0; mt < 2; mt++) {
                int base = warp_m + mt * 16;
                afr[mt][0] = As[base + r][kb + c4];
                afr[mt][1] = As[base + r + 8][kb + c4];
                afr[mt][2] = As[base + r][kb + c4 + 4];
                afr[mt][3] = As[base + r + 8][kb + c4 + 4];
            }
            uint32_t bfr[NT][2];
#pragma unroll
            for (int nt = 0; nt < NT; nt++) {
                int col = warp_n + nt * 8 + r;
                bfr[nt][0] = Bs[kb + c4][col];
                bfr[nt][1] = Bs[kb + c4 + 4][col];
            }
#pragma unroll
            for (int mt = 0; mt < 2; mt++)
#pragma unroll
                for (int nt = 0; nt < NT; nt++)
                    mma_tf32(acc[mt][nt], afr[mt], bfr[nt]);
        }
        __syncthreads();
    }

    // epilogue: scratch C is padded to NMAX rows, no store guard needed
#pragma unroll
    for (int mt = 0; mt < 2; mt++) {
        int row = m0 + warp_m + mt * 16 + r;
#pragma unroll
        for (int nt = 0; nt < NT; nt++) {
            int col = warp_n + nt * 8 + c4 * 2;
            *(float2*)&C[(size_t)row * BN + col] =
                make_float2(acc[mt][nt][0], acc[mt][nt][1]);
            *(float2*)&C[(size_t)(row + 8) * BN + col] =
                make_float2(acc[mt][nt][2], acc[mt][nt][3]);
        }
    }
}

// ---------------- aggregation: one warp per target node --------------------
__global__ void k_agg128(const float* __restrict__ bias, int N) {
    int warp = (blockIdx.x * blockDim.x + threadIdx.x) >> 5;
    int lane = threadIdx.x & 31;
    if (warp >= N) return;

    const float4* h4 = (const float4*)g_h1;
    float di = g_dinv[warp];
    float4 v = h4[(size_t)warp * 32 + lane];
    float w0 = di * di;
    float4 acc = make_float4(v.x * w0, v.y * w0, v.z * w0, v.w * w0);

    int s = g_ptr[warp], e = g_ptr[warp + 1];
    for (int j = s; j < e; j++) {
        int r = g_src[j];
        float wr = di * g_dinv[r];
        float4 hv = h4[(size_t)r * 32 + lane];
        acc.x = fmaf(wr, hv.x, acc.x);
        acc.y = fmaf(wr, hv.y, acc.y);
        acc.z = fmaf(wr, hv.z, acc.z);
        acc.w = fmaf(wr, hv.w, acc.w);
    }

    float4 b = ((const float4*)bias)[lane];
    acc.x = fmaxf(acc.x + b.x, 0.f);
    acc.y = fmaxf(acc.y + b.y, 0.f);
    acc.z = fmaxf(acc.z + b.z, 0.f);
    acc.w = fmaxf(acc.w + b.w, 0.f);
    ((float4*)g_a1)[(size_t)warp * 32 + lane] = acc;
}

__global__ void k_agg64(const float* __restrict__ bias, float* __restrict__ out,
                        int N) {
    int warp = (blockIdx.x * blockDim.x + threadIdx.x) >> 5;
    int lane = threadIdx.x & 31;
    if (warp >= N) return;

    const float2* h2 = (const float2*)g_h2;
    float di = g_dinv[warp];
    float2 v = h2[(size_t)warp * 32 + lane];
    float w0 = di * di;
    float2 acc = make_float2(v.x * w0, v.y * w0);

    int s = g_ptr[warp], e = g_ptr[warp + 1];
    for (int j = s; j < e; j++) {
        int r = g_src[j];
        float wr = di * g_dinv[r];
        float2 hv = h2[(size_t)r * 32 + lane];
        acc.x = fmaf(wr, hv.x, acc.x);
        acc.y = fmaf(wr, hv.y, acc.y);
    }

    float2 b = ((const float2*)bias)[lane];
    acc.x += b.x;
    acc.y += b.y;
    ((float2*)out)[(size_t)warp * 32 + lane] = acc;
}

// ---------------- launch ----------------------------------------------------
extern "C" void kernel_launch(void* const* d_in, const int* in_sizes, int n_in,
                              void* d_out, int out_size) {
    const float* x  = (const float*)d_in[0];
    const void*  ei = d_in[1];                   // int32 or int64, detected on device
    const float* W1 = (const float*)d_in[2];
    const float* b1 = (const float*)d_in[3];
    const float* W2 = (const float*)d_in[4];
    const float* b2 = (const float*)d_in[5];
    float*       out = (float*)d_out;

    int N = in_sizes[0] / 128;
    int E = in_sizes[1] / 2;

    // dtype probe + degree / dinv / CSR build
    k_detect<<<1, 32>>>((const unsigned int*)ei);
    k_zero<<<(N + 255) / 256, 256>>>(N);
    k_count<<<(E + 255) / 256, 256>>>(ei, E);
    k_dinv<<<(N + 255) / 256, 256>>>(N);
    int nb = (N + 1023) / 1024;
    k_scan1<<<nb, 1024>>>(N);
    k_scan2<<<1, 32>>>(nb);
    k_scan3<<<(N + 255) / 256, 256>>>(N);
    k_fill<<<(E + 255) / 256, 256>>>(ei, E);

    int gblocks = (N + 127) / 128;

    // layer 1
    k_gemm_tf32<128, false><<<gblocks, 256>>>(x, W1, N);
    k_agg128<<<(N * 32 + 255) / 256, 256>>>(b1, N);

    // layer 2
    k_gemm_tf32<64, true><<<gblocks, 256>>>(nullptr, W2, N);
    k_agg64<<<(N * 32 + 255) / 256, 256>>>(b2, out, N);
}

// round 4
// speedup vs baseline: 1.3766x; 1.1770x over previous
#include <cuda_runtime.h>
#include <cuda_fp16.h>
#include <cstdint>

// ---------------- problem-size constants (fixed by dataset) ----------------
#define NMAX 100352            // 784*128, >= 100000 nodes (padded for tile overrun)
#define EMAX 1700032           // >= 1,600,000 edges

// ---------------- scratch (static __device__ — no allocations) -------------
__device__ __align__(16) __half g_h1h[(size_t)NMAX * 128]; // dinv[r]*(x@W1), fp16
__device__ __align__(16) float  g_a1[(size_t)NMAX * 128];  // relu(agg1 + b1)
__device__ __align__(16) __half g_h2h[(size_t)NMAX * 64];  // dinv[r]*(a1@W2), fp16
__device__ float g_dinv[NMAX];
__device__ int   g_deg[NMAX];
__device__ int   g_cur[NMAX];
__device__ int   g_ptr[NMAX + 1];
__device__ int   g_src[EMAX];
__device__ int   g_scan[NMAX];
__device__ int   g_bsum[128];
__device__ int   g_is64;

// ---------------- edge dtype detection -------------------------------------
__global__ void k_detect(const unsigned int* __restrict__ w) {
    if (threadIdx.x == 0 && blockIdx.x == 0) {
        unsigned int nz = 0;
        for (int i = 1; i < 256; i += 2) nz |= w[i];
        g_is64 = (nz == 0) ? 1 : 0;
    }
}

__device__ __forceinline__ int edge_at(const void* __restrict__ ei, int i) {
    if (g_is64) return (int)((const long long*)ei)[i];
    return ((const int*)ei)[i];
}

// ---------------- CSR build -------------------------------------------------
__global__ void k_zero(int n) {
    int i = blockIdx.x * blockDim.x + threadIdx.x;
    if (i < n) { g_deg[i] = 0; g_cur[i] = 0; }
}

__global__ void k_count(const void* __restrict__ ei, int E) {
    int e = blockIdx.x * blockDim.x + threadIdx.x;
    if (e < E) atomicAdd(&g_deg[edge_at(ei, E + e)], 1);
}

// block-wise inclusive scan of g_deg + dinv computation (fused)
__global__ void k_scan1(int N) {
    __shared__ int s[1024];
    int t = threadIdx.x;
    int i = blockIdx.x * 1024 + t;
    int v = (i < N) ? g_deg[i] : 0;
    if (i < N) g_dinv[i] = rsqrtf((float)(v + 1));   // +1 self loop
    s[t] = v;
    __syncthreads();
#pragma unroll
    for (int off = 1; off < 1024; off <<= 1) {
        int x = (t >= off) ? s[t - off] : 0;
        __syncthreads();
        s[t] += x;
        __syncthreads();
    }
    g_scan[i] = s[t];
    if (t == 1023) g_bsum[blockIdx.x] = s[t];
}

// finalize ptr: block offset via warp-reduction over g_bsum (scan2 fused in)
__global__ void k_scan3(int N) {
    int i = blockIdx.x * 256 + threadIdx.x;
    int nb = blockIdx.x >> 2;          // completed scan1 blocks before this range
    int lane = threadIdx.x & 31;
    int s = 0;
    for (int j = lane; j < nb; j += 32) s += g_bsum[j];
#pragma unroll
    for (int o = 16; o; o >>= 1) s += __shfl_xor_sync(0xffffffffu, s, o);
    if (i < N) {
        g_ptr[i + 1] = g_scan[i] + s;
        if (i == 0) g_ptr[0] = 0;
    }
}

__global__ void k_fill(const void* __restrict__ ei, int E) {
    int e = blockIdx.x * blockDim.x + threadIdx.x;
    if (e < E) {
        int r = edge_at(ei, e);
        int c = edge_at(ei, E + e);
        int pos = g_ptr[c] + atomicAdd(&g_cur[c], 1);
        g_src[pos] = r;
    }
}

// ---------------- tf32 tensor-core GEMM ------------------------------------
// C_half[M,BN] = dinv[row] * (A[M,128] * B[128,BN])
__device__ __forceinline__ uint32_t f2tf32(float f) {
    uint32_t u;
    asm("cvt.rna.tf32.f32 %0, %1;" : "=r"(u) : "f"(f));
    return u;
}

__device__ __forceinline__ void mma_tf32(float* c, const uint32_t* a, const uint32_t* b) {
    asm volatile(
        "mma.sync.aligned.m16n8k8.row.col.f32.tf32.tf32.f32 "
        "{%0,%1,%2,%3}, {%4,%5,%6,%7}, {%8,%9}, {%0,%1,%2,%3};"
        : "+f"(c[0]), "+f"(c[1]), "+f"(c[2]), "+f"(c[3])
        : "r"(a[0]), "r"(a[1]), "r"(a[2]), "r"(a[3]), "r"(b[0]), "r"(b[1]));
}

template <int BN, bool A_GLOBAL>
__global__ void k_gemm_tf32(const float* __restrict__ Ain,
                            const float* __restrict__ B, int M) {
    constexpr int BM = 128, BK = 32;
    constexpr int NT = BN / 16;
    constexpr int BP = BN + 4;

    const float* A = A_GLOBAL ? (const float*)g_a1 : Ain;
    __half* C = (BN == 128) ? (__half*)g_h1h : (__half*)g_h2h;

    __shared__ uint32_t As[BM][BK + 4];
    __shared__ uint32_t Bs[BK][BP];

    int t    = threadIdx.x;
    int lane = t & 31;
    int wid  = t >> 5;
    int warp_m = (wid & 3) * 32;
    int warp_n = (wid >> 2) * (BN / 2);
    int m0   = blockIdx.x * BM;
    int r = lane >> 2, c4 = lane & 3;

    float acc[2][NT][4];
#pragma unroll
    for (int mt = 0; mt < 2; mt++)
#pragma unroll
        for (int nt = 0; nt < NT; nt++)
#pragma unroll
            for (int i = 0; i < 4; i++) acc[mt][nt][i] = 0.f;

    for (int k0 = 0; k0 < 128; k0 += BK) {
#pragma unroll
        for (int t4 = t; t4 < BM * BK / 4; t4 += 256) {
            int row = t4 >> 3;
            int kq  = t4 & 7;
            int gr  = m0 + row;
            float4 v = make_float4(0.f, 0.f, 0.f, 0.f);
            if (A_GLOBAL || gr < M)
                v = *(const float4*)&A[(size_t)gr * 128 + k0 + kq * 4];
            uint32_t* dst = &As[row][kq * 4];
            dst[0] = f2tf32(v.x); dst[1] = f2tf32(v.y);
            dst[2] = f2tf32(v.z); dst[3] = f2tf32(v.w);
        }
#pragma unroll
        for (int t4 = t; t4 < BK * BN / 4; t4 += 256) {
            int kk = t4 / (BN / 4);
            int nq = t4 % (BN / 4);
            float4 v = *(const float4*)&B[(size_t)(k0 + kk) * BN + nq * 4];
            uint32_t* dst = &Bs[kk][nq * 4];
            dst[0] = f2tf32(v.x); dst[1] = f2tf32(v.y);
            dst[2] = f2tf32(v.z); dst[3] = f2tf32(v.w);
        }
        __syncthreads();

#pragma unroll
        for (int kk = 0; kk < 4; kk++) {
            int kb = kk * 8;
            uint32_t afr[2][4];
#pragma unroll
            for (int mt = 0; mt < 2; mt++) {
                int base = warp_m + mt * 16;
                afr[mt][0] = As[base + r][kb + c4];
                afr[mt][1] = As[base + r + 8][kb + c4];
                afr[mt][2] = As[base + r][kb + c4 + 4];
                afr[mt][3] = As[base + r + 8][kb + c4 + 4];
            }
            uint32_t bfr[NT][2];
#pragma unroll
            for (int nt = 0; nt < NT; nt++) {
                int col = warp_n + nt * 8 + r;
                bfr[nt][0] = Bs[kb + c4][col];
                bfr[nt][1] = Bs[kb + c4 + 4][col];
            }
#pragma unroll
            for (int mt = 0; mt < 2; mt++)
#pragma unroll
                for (int nt = 0; nt < NT; nt++)
                    mma_tf32(acc[mt][nt], afr[mt], bfr[nt]);
        }
        __syncthreads();
    }

    // epilogue: scale by dinv[row], convert to fp16. Padded rows are written
    // with garbage dinv but never read by the aggregation kernels.
#pragma unroll
    for (int mt = 0; mt < 2; mt++) {
        int row = m0 + warp_m + mt * 16 + r;
        float d0 = g_dinv[row];
        float d1 = g_dinv[row + 8];
#pragma unroll
        for (int nt = 0; nt < NT; nt++) {
            int col = warp_n + nt * 8 + c4 * 2;
            *(__half2*)&C[(size_t)row * BN + col] =
                __floats2half2_rn(acc[mt][nt][0] * d0, acc[mt][nt][1] * d0);
            *(__half2*)&C[(size_t)(row + 8) * BN + col] =
                __floats2half2_rn(acc[mt][nt][2] * d1, acc[mt][nt][3] * d1);
        }
    }
}

// ---------------- aggregation: one warp per target node --------------------
// hs rows already carry dinv[row]; out[c] = dinv[c]*(hs[c] + sum hs[r]) + b
__global__ void k_agg128(const float* __restrict__ bias, int N) {
    int warp = (blockIdx.x * blockDim.x + threadIdx.x) >> 5;
    int lane = threadIdx.x & 31;
    if (warp >= N) return;

    const uint2* h = (const uint2*)g_h1h;        // 4 halves per lane
    uint2 u = h[(size_t)warp * 32 + lane];
    float2 flo = __half22float2(*(__half2*)&u.x);
    float2 fhi = __half22float2(*(__half2*)&u.y);
    float4 acc = make_float4(flo.x, flo.y, fhi.x, fhi.y);

    int s = g_ptr[warp], e = g_ptr[warp + 1];
#pragma unroll 4
    for (int j = s; j < e; j++) {
        int r = g_src[j];
        uint2 hu = h[(size_t)r * 32 + lane];
        float2 lo = __half22float2(*(__half2*)&hu.x);
        float2 hi = __half22float2(*(__half2*)&hu.y);
        acc.x += lo.x; acc.y += lo.y; acc.z += hi.x; acc.w += hi.y;
    }

    float di = g_dinv[warp];
    float4 b = ((const float4*)bias)[lane];
    acc.x = fmaxf(fmaf(di, acc.x, b.x), 0.f);
    acc.y = fmaxf(fmaf(di, acc.y, b.y), 0.f);
    acc.z = fmaxf(fmaf(di, acc.z, b.z), 0.f);
    acc.w = fmaxf(fmaf(di, acc.w, b.w), 0.f);
    ((float4*)g_a1)[(size_t)warp * 32 + lane] = acc;
}

__global__ void k_agg64(const float* __restrict__ bias, float* __restrict__ out,
                        int N) {
    int warp = (blockIdx.x * blockDim.x + threadIdx.x) >> 5;
    int lane = threadIdx.x & 31;
    if (warp >= N) return;

    const uint32_t* h = (const uint32_t*)g_h2h;  // 2 halves per lane
    uint32_t u = h[(size_t)warp * 32 + lane];
    float2 acc = __half22float2(*(__half2*)&u);

    int s = g_ptr[warp], e = g_ptr[warp + 1];
#pragma unroll 4
    for (int j = s; j < e; j++) {
        int r = g_src[j];
        uint32_t hu = h[(size_t)r * 32 + lane];
        float2 f = __half22float2(*(__half2*)&hu);
        acc.x += f.x; acc.y += f.y;
    }

    float di = g_dinv[warp];
    float2 b = ((const float2*)bias)[lane];
    acc.x = fmaf(di, acc.x, b.x);
    acc.y = fmaf(di, acc.y, b.y);
    ((float2*)out)[(size_t)warp * 32 + lane] = acc;
}

// ---------------- launch ----------------------------------------------------
extern "C" void kernel_launch(void* const* d_in, const int* in_sizes, int n_in,
                              void* d_out, int out_size) {
    const float* x  = (const float*)d_in[0];
    const void*  ei = d_in[1];                   // int32 or int64, detected on device
    const float* W1 = (const float*)d_in[2];
    const float* b1 = (const float*)d_in[3];
    const float* W2 = (const float*)d_in[4];
    const float* b2 = (const float*)d_in[5];
    float*       out = (float*)d_out;

    int N = in_sizes[0] / 128;
    int E = in_sizes[1] / 2;

    k_detect<<<1, 32>>>((const unsigned int*)ei);
    k_zero<<<(N + 255) / 256, 256>>>(N);
    k_count<<<(E + 255) / 256, 256>>>(ei, E);
    int nb = (N + 1023) / 1024;
    k_scan1<<<nb, 1024>>>(N);
    k_scan3<<<(N + 255) / 256, 256>>>(N);
    k_fill<<<(E + 255) / 256, 256>>>(ei, E);

    int gblocks = (N + 127) / 128;

    // layer 1
    k_gemm_tf32<128, false><<<gblocks, 256>>>(x, W1, N);
    k_agg128<<<(N * 32 + 255) / 256, 256>>>(b1, N);

    // layer 2
    k_gemm_tf32<64, true><<<gblocks, 256>>>(nullptr, W2, N);
    k_agg64<<<(N * 32 + 255) / 256, 256>>>(b2, out, N);
}

// round 5
// speedup vs baseline: 1.4778x; 1.0735x over previous
#include <cuda_runtime.h>
#include <cuda_fp16.h>
#include <cstdint>

// ---------------- problem-size constants (fixed by dataset) ----------------
#define NMAX 100352            // 784*128, >= 100000 nodes (padded for tile overrun)
#define EMAX 1700032           // >= 1,600,000 edges

// ---------------- scratch (static __device__ — no allocations) -------------
__device__ __align__(16) __half g_h1h[(size_t)NMAX * 128]; // x@W1, fp16 (no scale)
__device__ __align__(16) __half g_a1h[(size_t)NMAX * 128]; // relu(agg1+b1), fp16
__device__ __align__(16) __half g_h2h[(size_t)NMAX * 64];  // dinv[r]*(a1@W2), fp16
__device__ float g_dinv[NMAX];
__device__ int   g_deg[NMAX];
__device__ int   g_cur[NMAX];
__device__ int   g_ptr[NMAX + 1];
__device__ int   g_src[EMAX];
__device__ int   g_scan[NMAX];
__device__ int   g_bsum[128];
__device__ int   g_is64;

// ---------------- edge dtype detection -------------------------------------
__global__ void k_detect(const unsigned int* __restrict__ w) {
    if (threadIdx.x == 0 && blockIdx.x == 0) {
        unsigned int nz = 0;
        for (int i = 1; i < 256; i += 2) nz |= w[i];
        g_is64 = (nz == 0) ? 1 : 0;
    }
}

__device__ __forceinline__ int edge_at(const void* __restrict__ ei, int i) {
    if (g_is64) return (int)((const long long*)ei)[i];
    return ((const int*)ei)[i];
}

// ---------------- CSR build -------------------------------------------------
__global__ void k_zero(int n) {
    int i = blockIdx.x * blockDim.x + threadIdx.x;
    if (i < n) g_deg[i] = 0;
}

__global__ void k_count(const void* __restrict__ ei, int E) {
    int e = blockIdx.x * blockDim.x + threadIdx.x;
    if (e < E) atomicAdd(&g_deg[edge_at(ei, E + e)], 1);
}

// block-wise inclusive scan of g_deg (shuffle-based) + dinv (fused)
__global__ void k_scan1(int N) {
    __shared__ int wsum[32];
    int t = threadIdx.x;
    int i = blockIdx.x * 1024 + t;
    int lane = t & 31, w = t >> 5;
    int v = (i < N) ? g_deg[i] : 0;
    if (i < N) g_dinv[i] = rsqrtf((float)(v + 1));   // +1 self loop
    int x = v;
#pragma unroll
    for (int o = 1; o < 32; o <<= 1) {
        int y = __shfl_up_sync(0xffffffffu, x, o);
        if (lane >= o) x += y;
    }
    if (lane == 31) wsum[w] = x;
    __syncthreads();
    if (w == 0) {
        int s = wsum[lane];
#pragma unroll
        for (int o = 1; o < 32; o <<= 1) {
            int y = __shfl_up_sync(0xffffffffu, s, o);
            if (lane >= o) s += y;
        }
        wsum[lane] = s;
    }
    __syncthreads();
    if (w > 0) x += wsum[w - 1];
    g_scan[i] = x;
    if (t == 1023) g_bsum[blockIdx.x] = x;
}

// finalize ptr (block offsets via warp reduction) + zero cursors (fused)
__global__ void k_scan3(int N) {
    int i = blockIdx.x * 256 + threadIdx.x;
    int nb = blockIdx.x >> 2;          // completed scan1 blocks before this range
    int lane = threadIdx.x & 31;
    int s = 0;
    for (int j = lane; j < nb; j += 32) s += g_bsum[j];
#pragma unroll
    for (int o = 16; o; o >>= 1) s += __shfl_xor_sync(0xffffffffu, s, o);
    if (i < N) {
        g_ptr[i + 1] = g_scan[i] + s;
        g_cur[i] = 0;
        if (i == 0) g_ptr[0] = 0;
    }
}

__global__ void k_fill(const void* __restrict__ ei, int E) {
    int e = blockIdx.x * blockDim.x + threadIdx.x;
    if (e < E) {
        int r = edge_at(ei, e);
        int c = edge_at(ei, E + e);
        int pos = g_ptr[c] + atomicAdd(&g_cur[c], 1);
        g_src[pos] = r;
    }
}

// ---------------- tf32 tensor-core GEMM ------------------------------------
__device__ __forceinline__ uint32_t f2tf32(float f) {
    uint32_t u;
    asm("cvt.rna.tf32.f32 %0, %1;" : "=r"(u) : "f"(f));
    return u;
}

__device__ __forceinline__ void mma_tf32(float* c, const uint32_t* a, const uint32_t* b) {
    asm volatile(
        "mma.sync.aligned.m16n8k8.row.col.f32.tf32.tf32.f32 "
        "{%0,%1,%2,%3}, {%4,%5,%6,%7}, {%8,%9}, {%0,%1,%2,%3};"
        : "+f"(c[0]), "+f"(c[1]), "+f"(c[2]), "+f"(c[3])
        : "r"(a[0]), "r"(a[1]), "r"(a[2]), "r"(a[3]), "r"(b[0]), "r"(b[1]));
}

// C_half[M,BN] = (PRESCALE ? dinv[row] : 1) * (A[M,128] * B[128,BN])
// A_HALF: A = g_a1h (fp16, padded rows safe); else A = Ain (fp32, guarded).
template <int BN, bool A_HALF, bool PRESCALE>
__global__ void k_gemm_tf32(const float* __restrict__ Ain,
                            const float* __restrict__ B, int M) {
    constexpr int BM = 128, BK = 32;
    constexpr int NT = BN / 16;
    constexpr int BP = BN + 4;

    __half* C = (BN == 128) ? (__half*)g_h1h : (__half*)g_h2h;

    __shared__ uint32_t As[BM][BK + 4];
    __shared__ uint32_t Bs[BK][BP];

    int t    = threadIdx.x;
    int lane = t & 31;
    int wid  = t >> 5;
    int warp_m = (wid & 3) * 32;
    int warp_n = (wid >> 2) * (BN / 2);
    int m0   = blockIdx.x * BM;
    int r = lane >> 2, c4 = lane & 3;

    float acc[2][NT][4];
#pragma unroll
    for (int mt = 0; mt < 2; mt++)
#pragma unroll
        for (int nt = 0; nt < NT; nt++)
#pragma unroll
            for (int i = 0; i < 4; i++) acc[mt][nt][i] = 0.f;

    for (int k0 = 0; k0 < 128; k0 += BK) {
        // A tile (BM x BK) -> tf32
#pragma unroll
        for (int t4 = t; t4 < BM * BK / 4; t4 += 256) {
            int row = t4 >> 3;
            int kq  = t4 & 7;
            int gr  = m0 + row;
            uint32_t* dst = &As[row][kq * 4];
            if (A_HALF) {
                uint2 u = *(const uint2*)&g_a1h[(size_t)gr * 128 + k0 + kq * 4];
                float2 f0 = __half22float2(*(__half2*)&u.x);
                float2 f1 = __half22float2(*(__half2*)&u.y);
                dst[0] = f2tf32(f0.x); dst[1] = f2tf32(f0.y);
                dst[2] = f2tf32(f1.x); dst[3] = f2tf32(f1.y);
            } else {
                float4 v = make_float4(0.f, 0.f, 0.f, 0.f);
                if (gr < M)
                    v = *(const float4*)&Ain[(size_t)gr * 128 + k0 + kq * 4];
                dst[0] = f2tf32(v.x); dst[1] = f2tf32(v.y);
                dst[2] = f2tf32(v.z); dst[3] = f2tf32(v.w);
            }
        }
        // B tile (BK x BN) -> tf32
#pragma unroll
        for (int t4 = t; t4 < BK * BN / 4; t4 += 256) {
            int kk = t4 / (BN / 4);
            int nq = t4 % (BN / 4);
            float4 v = *(const float4*)&B[(size_t)(k0 + kk) * BN + nq * 4];
            uint32_t* dst = &Bs[kk][nq * 4];
            dst[0] = f2tf32(v.x); dst[1] = f2tf32(v.y);
            dst[2] = f2tf32(v.z); dst[3] = f2tf32(v.w);
        }
        __syncthreads();

#pragma unroll
        for (int kk = 0; kk < 4; kk++) {
            int kb = kk * 8;
            uint32_t afr[2][4];
#pragma unroll
            for (int mt = 0; mt < 2; mt++) {
                int base = warp_m + mt * 16;
                afr[mt][0] = As[base + r][kb + c4];
                afr[mt][1] = As[base + r + 8][kb + c4];
                afr[mt][2] = As[base + r][kb + c4 + 4];
                afr[mt][3] = As[base + r + 8][kb + c4 + 4];
            }
            uint32_t bfr[NT][2];
#pragma unroll
            for (int nt = 0; nt < NT; nt++) {
                int col = warp_n + nt * 8 + r;
                bfr[nt][0] = Bs[kb + c4][col];
                bfr[nt][1] = Bs[kb + c4 + 4][col];
            }
#pragma unroll
            for (int mt = 0; mt < 2; mt++)
#pragma unroll
                for (int nt = 0; nt < NT; nt++)
                    mma_tf32(acc[mt][nt], afr[mt], bfr[nt]);
        }
        __syncthreads();
    }

    // epilogue -> fp16 (padded rows: dinv=0 there, never read downstream)
#pragma unroll
    for (int mt = 0; mt < 2; mt++) {
        int row = m0 + warp_m + mt * 16 + r;
        float d0 = PRESCALE ? g_dinv[row]     : 1.f;
        float d1 = PRESCALE ? g_dinv[row + 8] : 1.f;
#pragma unroll
        for (int nt = 0; nt < NT; nt++) {
            int col = warp_n + nt * 8 + c4 * 2;
            *(__half2*)&C[(size_t)row * BN + col] =
                __floats2half2_rn(acc[mt][nt][0] * d0, acc[mt][nt][1] * d0);
            *(__half2*)&C[(size_t)(row + 8) * BN + col] =
                __floats2half2_rn(acc[mt][nt][2] * d1, acc[mt][nt][3] * d1);
        }
    }
}

// ---------------- aggregation: one warp per target node --------------------
// layer 1: h1 is UNscaled -> load dinv[r] per edge (lane-broadcast).
// out[c] = relu(dinv[c]*(dinv[c]*h[c] + sum dinv[r]*h[r]) + b), stored fp16.
__global__ void k_agg128(const float* __restrict__ bias, int N) {
    int warp = (blockIdx.x * blockDim.x + threadIdx.x) >> 5;
    int lane = threadIdx.x & 31;
    if (warp >= N) return;

    const uint2* h = (const uint2*)g_h1h;
    float di = g_dinv[warp];
    uint2 u = h[(size_t)warp * 32 + lane];
    float2 flo = __half22float2(*(__half2*)&u.x);
    float2 fhi = __half22float2(*(__half2*)&u.y);
    float4 acc = make_float4(di * flo.x, di * flo.y, di * fhi.x, di * fhi.y);

    int s = g_ptr[warp], e = g_ptr[warp + 1];
#pragma unroll 4
    for (int j = s; j < e; j++) {
        int r = g_src[j];
        float wr = g_dinv[r];
        uint2 hu = h[(size_t)r * 32 + lane];
        float2 lo = __half22float2(*(__half2*)&hu.x);
        float2 hi = __half22float2(*(__half2*)&hu.y);
        acc.x = fmaf(wr, lo.x, acc.x);
        acc.y = fmaf(wr, lo.y, acc.y);
        acc.z = fmaf(wr, hi.x, acc.z);
        acc.w = fmaf(wr, hi.y, acc.w);
    }

    float4 b = ((const float4*)bias)[lane];
    float ox = fmaxf(fmaf(di, acc.x, b.x), 0.f);
    float oy = fmaxf(fmaf(di, acc.y, b.y), 0.f);
    float oz = fmaxf(fmaf(di, acc.z, b.z), 0.f);
    float ow = fmaxf(fmaf(di, acc.w, b.w), 0.f);
    __half2 p0 = __floats2half2_rn(ox, oy);
    __half2 p1 = __floats2half2_rn(oz, ow);
    uint2 st;
    st.x = *(uint32_t*)&p0;
    st.y = *(uint32_t*)&p1;
    ((uint2*)g_a1h)[(size_t)warp * 32 + lane] = st;
}

// layer 2: h2 rows already carry dinv[row] -> pure adds, fp32 out.
__global__ void k_agg64(const float* __restrict__ bias, float* __restrict__ out,
                        int N) {
    int warp = (blockIdx.x * blockDim.x + threadIdx.x) >> 5;
    int lane = threadIdx.x & 31;
    if (warp >= N) return;

    const uint32_t* h = (const uint32_t*)g_h2h;
    uint32_t u = h[(size_t)warp * 32 + lane];
    float2 acc = __half22float2(*(__half2*)&u);

    int s = g_ptr[warp], e = g_ptr[warp + 1];
#pragma unroll 4
    for (int j = s; j < e; j++) {
        int r = g_src[j];
        uint32_t hu = h[(size_t)r * 32 + lane];
        float2 f = __half22float2(*(__half2*)&hu);
        acc.x += f.x; acc.y += f.y;
    }

    float di = g_dinv[warp];
    float2 b = ((const float2*)bias)[lane];
    acc.x = fmaf(di, acc.x, b.x);
    acc.y = fmaf(di, acc.y, b.y);
    ((float2*)out)[(size_t)warp * 32 + lane] = acc;
}

// ---------------- launch ----------------------------------------------------
extern "C" void kernel_launch(void* const* d_in, const int* in_sizes, int n_in,
                              void* d_out, int out_size) {
    const float* x  = (const float*)d_in[0];
    const void*  ei = d_in[1];                   // int32 or int64, detected on device
    const float* W1 = (const float*)d_in[2];
    const float* b1 = (const float*)d_in[3];
    const float* W2 = (const float*)d_in[4];
    const float* b2 = (const float*)d_in[5];
    float*       out = (float*)d_out;

    int N = in_sizes[0] / 128;
    int E = in_sizes[1] / 2;
    int nb = (N + 1023) / 1024;
    int gblocks = (N + 127) / 128;

    // capture-fork: CSR build on side stream, GEMM1 concurrently on main.
    cudaStream_t s2;
    cudaStreamCreateWithFlags(&s2, cudaStreamNonBlocking);
    cudaEvent_t evFork, evJoin;
    cudaEventCreateWithFlags(&evFork, cudaEventDisableTiming);
    cudaEventCreateWithFlags(&evJoin, cudaEventDisableTiming);

    cudaEventRecord(evFork, 0);
    cudaStreamWaitEvent(s2, evFork, 0);

    // side stream: edge dtype probe + degree/dinv + CSR
    k_detect<<<1, 32, 0, s2>>>((const unsigned int*)ei);
    k_zero<<<(N + 255) / 256, 256, 0, s2>>>(N);
    k_count<<<(E + 255) / 256, 256, 0, s2>>>(ei, E);
    k_scan1<<<nb, 1024, 0, s2>>>(N);
    k_scan3<<<(N + 255) / 256, 256, 0, s2>>>(N);
    k_fill<<<(E + 255) / 256, 256, 0, s2>>>(ei, E);
    cudaEventRecord(evJoin, s2);

    // main stream: GEMM1 (independent of CSR — no dinv in epilogue)
    k_gemm_tf32<128, false, false><<<gblocks, 256>>>(x, W1, N);

    // join, then the dependent chain
    cudaStreamWaitEvent(0, evJoin, 0);
    k_agg128<<<(N * 32 + 255) / 256, 256>>>(b1, N);
    k_gemm_tf32<64, true, true><<<gblocks, 256>>>(nullptr, W2, N);
    k_agg64<<<(N * 32 + 255) / 256, 256>>>(b2, out, N);
    // (stream/events intentionally not destroyed: kernel_launch is invoked
    //  only for correctness + capture; destroying mid-capture is unsafe)
}